// round 16
// baseline (speedup 1.0000x reference)
#include <cuda_runtime.h>

// Problem constants (fixed by setup_inputs)
#define BATCH   16
#define CHAN    4
#define H_IN    128
#define W_IN    240
#define MAXD    24
#define H_OUT   1024
#define W_OUT   1920
#define W4      (W_OUT / 4)     // 480
#define HW      (H_IN * W_IN)
#define PAD     (MAXD - 1)      // 23 zero-pad float4s for negative shifts

#define NBLK    296             // 2 per SM on 148+ SMs -> all co-resident
#define NTHREADS 512
#define NPAIRS  (BATCH * H_IN / 2)   // 1024 row pairs (disp phase)
#define NVB     (BATCH * H_IN * W4 / NTHREADS)  // 1920 virtual resize blocks

// Low-res disparity prediction scratch (pred * 8): ~2 MB.
__device__ float g_pred[BATCH * H_IN * W_IN];

// Self-resetting device-wide barrier state (zero-initialized by loader;
// returns to cnt=0 after every full barrier -> deterministic across replays).
__device__ unsigned g_cnt = 0;
__device__ volatile unsigned g_gen = 0;

__device__ __forceinline__ void grid_barrier()
{
    __syncthreads();
    if (threadIdx.x == 0) {
        __threadfence();                      // publish g_pred writes
        const unsigned gen = g_gen;           // read BEFORE arriving
        if (atomicAdd(&g_cnt, 1) == NBLK - 1) {
            g_cnt = 0;
            __threadfence();
            g_gen = gen + 1;                  // release
        } else {
            while (g_gen == gen) __nanosleep(32);
        }
    }
    __syncthreads();
    __threadfence();                          // acquire before g_pred reads
}

// ---------------------------------------------------------------------------
// Single fused launch, 296 co-resident blocks of 512 threads.
//  Phase A: grid-stride over 1024 (b, row-pair)s: cost volume + unshifted
//           softmax expectation (padded smem right rows, no predicates).
//  Phase B: after device barrier, grid-stride over 1920 virtual resize
//           blocks: R7 bilinear upsample (register pred window, hoisted
//           x-geometry, 512B-contiguous warp stores).
// ---------------------------------------------------------------------------
__global__ __launch_bounds__(NTHREADS, 2) void fused_kernel(
    const float* __restrict__ fl, const float* __restrict__ fr,
    float* __restrict__ out)
{
    const int bid = blockIdx.x;
    const int tid = threadIdx.x;

    // ================= Phase A: disparity prediction =================
    {
        __shared__ float4 sr4[2][PAD + W_IN];
        const int half = tid >> 8;           // row within pair
        const int x    = tid & 255;

        for (int p = bid; p < NPAIRS; p += NBLK) {
            const int b  = p >> 6;
            const int yp = p & 63;
            const int y  = yp * 2 + half;

            if (x < PAD) sr4[half][x] = make_float4(0.f, 0.f, 0.f, 0.f);

            float4 L;
            if (x < W_IN) {
                const size_t rb = (size_t)b * (CHAN * HW) + (size_t)y * W_IN + x;
                float4 R;
                R.x = fr[rb];          R.y = fr[rb + HW];
                R.z = fr[rb + 2 * HW]; R.w = fr[rb + 3 * HW];
                sr4[half][PAD + x] = R;
                L.x = fl[rb];          L.y = fl[rb + HW];
                L.z = fl[rb + 2 * HW]; L.w = fl[rb + 3 * HW];
            }
            __syncthreads();

            if (x < W_IN) {
                const float4* __restrict__ rrow = &sr4[half][PAD + x];
                float num = 0.0f, den = 0.0f;
#pragma unroll
                for (int d = 0; d < MAXD; d++) {
                    const float4 R = rrow[-d];     // pad keeps this in-bounds
                    const float c = fabsf(L.x - R.x) + fabsf(L.y - R.y)
                                  + fabsf(L.z - R.z) + fabsf(L.w - R.w);
                    const float e = __expf(-c);    // softmax(-cost), unshifted
                    den += e;
                    num += (float)d * e;
                }
                g_pred[(b * H_IN + y) * W_IN + x] = (num / den) * 8.0f;
            }
            __syncthreads();                  // smem reuse across iterations
        }
    }

    // ================= device-wide barrier =================
    grid_barrier();

    // ================= Phase B: bilinear upsample =================
    const float xsc = 239.0f / 1919.0f;
    const float ysc = 127.0f / 1023.0f;

    for (int vb = bid; vb < NVB; vb += NBLK) {
        const int idx = vb * NTHREADS + tid;  // 0 .. 983039
        const int g = idx % W4;
        const int t = idx / W4;
        const int r = t & (H_IN - 1);
        const int b = t >> 7;

        // hoisted x-geometry for 4 contiguous output pixels
        const int ox0 = g * 4;
        const int q = (ox0 * 239) / 1919;     // exact base input cell
        float wx[4];
        bool  hi[4];
#pragma unroll
        for (int k = 0; k < 4; k++) {
            const float xf = (float)(ox0 + k) * xsc;
            const int x0 = (int)xf;
            wx[k] = xf - (float)x0;
            hi[k] = (x0 > q);                 // pixel lies in cell q+1
        }

        const int q1 = min(q + 1, W_IN - 1);
        const int q2 = min(q + 2, W_IN - 1);
        const int r1 = min(r + 1, H_IN - 1);

        // pred window (2 rows x 3 cols) into registers
        const float* __restrict__ p0r = g_pred + (b * H_IN + r)  * W_IN;
        const float* __restrict__ p1r = g_pred + (b * H_IN + r1) * W_IN;
        const float p00 = p0r[q], p01 = p0r[q1], p02 = p0r[q2];
        const float D0 = p1r[q]  - p00;
        const float D1 = p1r[q1] - p01;
        const float D2 = p1r[q2] - p02;

        // output rows owned by input row r: floor(oy*127/1023) == r
        const int oys = (r * (H_OUT - 1) + (H_IN - 2)) / (H_IN - 1);
        const int oye = min(H_OUT - 1,
            ((r + 1) * (H_OUT - 1) + (H_IN - 2)) / (H_IN - 1) - 1);

        float4* __restrict__ out4 =
            (float4*)out + (size_t)b * H_OUT * W4 + g;

        for (int oy = oys; oy <= oye; oy++) {
            const float wy = (float)oy * ysc - (float)r;
            const float v0 = p00 + wy * D0;   // y-lerp (3 FMA)
            const float v1 = p01 + wy * D1;
            const float v2 = p02 + wy * D2;
            const float d01 = v1 - v0;
            const float d12 = v2 - v1;

            float4 o;
#pragma unroll
            for (int k = 0; k < 4; k++) {
                const float base = hi[k] ? v1 : v0;
                const float del  = hi[k] ? d12 : d01;
                ((float*)&o)[k] = base + wx[k] * del;
            }
            out4[(size_t)oy * W4] = o;        // warp: 512B contiguous
        }
    }
}

extern "C" void kernel_launch(void* const* d_in, const int* in_sizes, int n_in,
                              void* d_out, int out_size)
{
    const float* feat_l = (const float*)d_in[0];
    const float* feat_r = (const float*)d_in[1];
    float* out = (float*)d_out;

    fused_kernel<<<NBLK, NTHREADS>>>(feat_l, feat_r, out);
}

// round 17
// speedup vs baseline: 1.0638x; 1.0638x over previous
#include <cuda_runtime.h>

// Problem constants (fixed by setup_inputs)
#define BATCH   16
#define CHAN    4
#define H_IN    128
#define W_IN    240
#define MAXD    24
#define H_OUT   1024
#define W_OUT   1920
#define W4      (W_OUT / 4)     // 480
#define HW      (H_IN * W_IN)
#define PAD     (MAXD - 1)      // 23 zero-pad float4s for negative shifts

// Low-res disparity prediction scratch (pred * 8): ~2 MB.
__device__ float g_pred[BATCH * H_IN * W_IN];

// ---------------------------------------------------------------------------
// K1: cost volume + softmax expectation. One block per (b, row-pair).
// Right rows staged zero-padded in smem (channel-packed float4) so the
// 24-deep disparity loop has no predicates. Unshifted softmax
// (cost >= 0 -> exp in (0,1], no overflow).
// ---------------------------------------------------------------------------
__global__ __launch_bounds__(512) void disp_kernel(
    const float* __restrict__ fl, const float* __restrict__ fr)
{
    const int pair = blockIdx.x;         // b*64 + yp
    const int b  = pair >> 6;
    const int yp = pair & 63;
    const int half = threadIdx.x >> 8;   // row within pair
    const int x    = threadIdx.x & 255;
    const int y = yp * 2 + half;

    __shared__ float4 sr4[2][PAD + W_IN];

    if (x < PAD) sr4[half][x] = make_float4(0.f, 0.f, 0.f, 0.f);

    float4 L;
    if (x < W_IN) {
        const size_t rb = (size_t)b * (CHAN * HW) + (size_t)y * W_IN + x;
        float4 R;
        R.x = fr[rb];          R.y = fr[rb + HW];
        R.z = fr[rb + 2 * HW]; R.w = fr[rb + 3 * HW];
        sr4[half][PAD + x] = R;
        L.x = fl[rb];          L.y = fl[rb + HW];
        L.z = fl[rb + 2 * HW]; L.w = fl[rb + 3 * HW];
    }
    __syncthreads();

    if (x < W_IN) {
        const float4* __restrict__ rrow = &sr4[half][PAD + x];

        float num = 0.0f, den = 0.0f;
#pragma unroll
        for (int d = 0; d < MAXD; d++) {
            const float4 R = rrow[-d];            // pad keeps this in-bounds
            const float c = fabsf(L.x - R.x) + fabsf(L.y - R.y)
                          + fabsf(L.z - R.z) + fabsf(L.w - R.w);
            const float e = __expf(-c);           // softmax(-cost), unshifted
            den += e;
            num += (float)d * e;
        }
        g_pred[(b * H_IN + y) * W_IN + x] = (num / den) * 8.0f;  // * 1024/128
    }
}

// ---------------------------------------------------------------------------
// K2: bilinear upsample 128x240 -> 1024x1920 (align_corners).
// One thread per (b, input-row r, float4 column g); warp store = 512B
// contiguous. Register-lean: unified 2-cell coordinate t in [0,2),
//   val = v0 + t*d01 + max(t-1,0)*(d12-d01)   (exact piecewise lerp),
// no bools/selects. __launch_bounds__(256,8) pins regs <= 32 so the SM
// runs 2048 threads -> max outstanding-store parallelism.
// ---------------------------------------------------------------------------
__global__ __launch_bounds__(256, 8) void resize_kernel(float* __restrict__ out)
{
    const int idx = blockIdx.x * 256 + threadIdx.x;   // exact grid, no guard
    const int g = idx % W4;
    const int t0 = idx / W4;
    const int r = t0 & (H_IN - 1);
    const int b = t0 >> 7;

    const float xsc = 239.0f / 1919.0f;
    const float ysc = 127.0f / 1023.0f;

    // unified x-coordinates within the 2-cell span starting at q
    const int ox0 = g * 4;
    const int q = (ox0 * 239) / 1919;            // exact base input cell
    float t[4];
#pragma unroll
    for (int k = 0; k < 4; k++)
        t[k] = (float)(ox0 + k) * xsc - (float)q;     // in [0, 2)

    const int q1 = min(q + 1, W_IN - 1);
    const int q2 = min(q + 2, W_IN - 1);
    const int r1 = min(r + 1, H_IN - 1);

    // pred window (2 rows x 3 cols) into registers
    const float* __restrict__ p0r = g_pred + (b * H_IN + r)  * W_IN;
    const float* __restrict__ p1r = g_pred + (b * H_IN + r1) * W_IN;
    const float p00 = __ldg(p0r + q), p01 = __ldg(p0r + q1), p02 = __ldg(p0r + q2);
    const float D0 = __ldg(p1r + q)  - p00;
    const float D1 = __ldg(p1r + q1) - p01;
    const float D2 = __ldg(p1r + q2) - p02;

    // output rows owned by input row r: floor(oy*127/1023) == r
    const int oys = (r * (H_OUT - 1) + (H_IN - 2)) / (H_IN - 1);
    const int oye = min(H_OUT - 1,
        ((r + 1) * (H_OUT - 1) + (H_IN - 2)) / (H_IN - 1) - 1);

    float4* __restrict__ out4 =
        (float4*)out + (size_t)b * H_OUT * W4 + g;

    for (int oy = oys; oy <= oye; oy++) {
        const float wy = (float)oy * ysc - (float)r;
        const float v0 = p00 + wy * D0;          // y-lerp (3 FMA)
        const float v1 = p01 + wy * D1;
        const float v2 = p02 + wy * D2;
        const float d01 = v1 - v0;
        const float e   = (v2 - v1) - d01;       // slope change at cell q+1

        float4 o;
#pragma unroll
        for (int k = 0; k < 4; k++) {
            const float u  = t[k];
            const float u1 = fmaxf(u - 1.0f, 0.0f);
            ((float*)&o)[k] = fmaf(u1, e, fmaf(u, d01, v0));
        }
        out4[(size_t)oy * W4] = o;               // warp: 512B contiguous
    }
}

extern "C" void kernel_launch(void* const* d_in, const int* in_sizes, int n_in,
                              void* d_out, int out_size)
{
    const float* feat_l = (const float*)d_in[0];
    const float* feat_r = (const float*)d_in[1];
    float* out = (float*)d_out;

    disp_kernel<<<BATCH * (H_IN / 2), 512>>>(feat_l, feat_r);

    const int total = BATCH * H_IN * W4;         // 983,040
    resize_kernel<<<total / 256, 256>>>(out);
}